// round 2
// baseline (speedup 1.0000x reference)
#include <cuda_runtime.h>
#include <cstdint>

#define N_DRUG 25000
#define N_DIS  25000
#define NN     50000
#define NE     800000
#define D      128

// Scratch: __device__ globals (no allocations allowed).
__device__ __align__(16) float g_deg[NN];
__device__ __align__(16) float g_h[(size_t)NN * D];   // norm-scaled projected features

static __device__ __forceinline__ int clamp_idx(int v) {
    return v < 0 ? 0 : (v >= NN ? NN - 1 : v);
}

// ---------------------------------------------------------------------------
// Zero scratch + output (d_out is poisoned 0xAA by the harness).
// ---------------------------------------------------------------------------
__global__ void init_kernel(float4* __restrict__ out4) {
    int stride = gridDim.x * blockDim.x;
    int i = blockIdx.x * blockDim.x + threadIdx.x;
    const int total4 = NN * D / 4;
    float4 z = make_float4(0.f, 0.f, 0.f, 0.f);
    for (int t = i; t < total4; t += stride) out4[t] = z;
    for (int t = i; t < NN; t += stride) g_deg[t] = 0.f;
}

// ---------------------------------------------------------------------------
// Degree histogram: deg[r] += 1 for each edge row r.  (indices are int32)
// ---------------------------------------------------------------------------
__global__ void deg_kernel(const int* __restrict__ rows) {
    int e = blockIdx.x * blockDim.x + threadIdx.x;
    if (e < NE) {
        atomicAdd(&g_deg[clamp_idx(rows[e])], 1.0f);
    }
}

// ---------------------------------------------------------------------------
// Projection: g_h[node_base+row][:] = (f[row] @ W) * norm[node_base+row]
// Block: 256 threads = 4 row-groups x 64 columns. gridDim.y = 2 column halves.
// W tile [128 x 64] in smem (32 KB), f rows staged in smem.
// ---------------------------------------------------------------------------
#define PROJ_TB  256
#define PROJ_RPB 32
#define PROJ_CH  64

__global__ __launch_bounds__(PROJ_TB)
void proj_kernel(const float* __restrict__ f, const float* __restrict__ W,
                 int n_rows, int node_base) {
    __shared__ float sW[D * PROJ_CH];      // [k][j], j = column within half
    __shared__ float sF[4][D];             // one f row per row-group

    const int j = threadIdx.x & 63;        // column within half
    const int g = threadIdx.x >> 6;        // row-group 0..3
    const int colbase = blockIdx.y * PROJ_CH;

    // Cooperative load of the W tile (coalesced 64-wide).
    for (int idx = threadIdx.x; idx < D * PROJ_CH; idx += PROJ_TB) {
        int k  = idx >> 6;
        int jj = idx & 63;
        sW[idx] = W[k * D + colbase + jj];
    }
    __syncthreads();

    const int row0 = blockIdx.x * PROJ_RPB;

    for (int it = 0; it < PROJ_RPB / 4; ++it) {
        int row = row0 + it * 4 + g;
        bool valid = (row < n_rows);

        // Stage this group's f row (64 threads load 2 floats each).
        if (valid) {
            sF[g][j]      = f[(size_t)row * D + j];
            sF[g][j + 64] = f[(size_t)row * D + j + 64];
        }
        __syncthreads();

        if (valid) {
            const float4* sf4 = (const float4*)sF[g];
            float acc = 0.f;
            #pragma unroll
            for (int k4 = 0; k4 < D / 4; ++k4) {
                float4 fv = sf4[k4];
                acc += fv.x * sW[(k4 * 4 + 0) * PROJ_CH + j];
                acc += fv.y * sW[(k4 * 4 + 1) * PROJ_CH + j];
                acc += fv.z * sW[(k4 * 4 + 2) * PROJ_CH + j];
                acc += fv.w * sW[(k4 * 4 + 3) * PROJ_CH + j];
            }
            int node = node_base + row;
            float nrm = rsqrtf(fmaxf(g_deg[node], 1.0f));
            g_h[(size_t)node * D + colbase + j] = acc * nrm;
        }
        __syncthreads();
    }
}

// ---------------------------------------------------------------------------
// Scatter: one warp per edge. Gather 128 floats from g_h[col], vector-reduce
// into out[row] with red.global.add.v4.f32 (no return value, L2-resident).
// ---------------------------------------------------------------------------
__global__ __launch_bounds__(256)
void scatter_kernel(const int* __restrict__ rows,
                    const int* __restrict__ cols,
                    float* __restrict__ out) {
    int gw   = (blockIdx.x * blockDim.x + threadIdx.x) >> 5;  // global warp = edge
    int lane = threadIdx.x & 31;
    if (gw >= NE) return;

    int r = clamp_idx(__ldg(&rows[gw]));   // same addr across warp -> broadcast
    int c = clamp_idx(__ldg(&cols[gw]));

    const float4 v = *(const float4*)&g_h[(size_t)c * D + lane * 4];
    float* dst = &out[(size_t)r * D + lane * 4];
    asm volatile("red.global.add.v4.f32 [%0], {%1,%2,%3,%4};"
                 :: "l"(dst), "f"(v.x), "f"(v.y), "f"(v.z), "f"(v.w)
                 : "memory");
}

// ---------------------------------------------------------------------------
// Final symmetric-norm scale: out[i][:] *= norm[i]
// ---------------------------------------------------------------------------
__global__ __launch_bounds__(256)
void scale_kernel(float* __restrict__ out) {
    int idx  = blockIdx.x * blockDim.x + threadIdx.x;  // one per float4
    int row  = idx >> 5;
    int lane = idx & 31;
    if (row >= NN) return;
    float nrm = rsqrtf(fmaxf(g_deg[row], 1.0f));
    float4* p = (float4*)&out[(size_t)row * D + lane * 4];
    float4 v = *p;
    v.x *= nrm; v.y *= nrm; v.z *= nrm; v.w *= nrm;
    *p = v;
}

// ---------------------------------------------------------------------------
// Launch sequence (stream 0, graph-capturable, allocation-free).
// Input order per metadata: drug_f, disease_f, drug_w, disease_w, rows, cols.
// ---------------------------------------------------------------------------
extern "C" void kernel_launch(void* const* d_in, const int* in_sizes, int n_in,
                              void* d_out, int out_size) {
    const float* drug_f = (const float*)d_in[0];
    const float* dis_f  = (const float*)d_in[1];
    const float* drug_w = (const float*)d_in[2];
    const float* dis_w  = (const float*)d_in[3];
    const int*   rows   = (const int*)d_in[4];
    const int*   cols   = (const int*)d_in[5];
    float* out = (float*)d_out;

    // 1) zero deg + output
    init_kernel<<<1024, 256>>>((float4*)out);

    // 2) degree histogram
    deg_kernel<<<(NE + 255) / 256, 256>>>(rows);

    // 3) per-type projection (+ pre-scale by norm)
    dim3 pgrid((N_DRUG + PROJ_RPB - 1) / PROJ_RPB, 2);
    proj_kernel<<<pgrid, PROJ_TB>>>(drug_f, drug_w, N_DRUG, 0);
    dim3 pgrid2((N_DIS + PROJ_RPB - 1) / PROJ_RPB, 2);
    proj_kernel<<<pgrid2, PROJ_TB>>>(dis_f, dis_w, N_DIS, N_DRUG);

    // 4) edge scatter (warp per edge, vector atomics)
    scatter_kernel<<<(NE * 32 + 255) / 256, 256>>>(rows, cols, out);

    // 5) post-scale by norm
    scale_kernel<<<(NN * 32 + 255) / 256, 256>>>(out);
}

// round 4
// speedup vs baseline: 1.7468x; 1.7468x over previous
#include <cuda_runtime.h>
#include <cstdint>

#define N_DRUG 25000
#define N_DIS  25000
#define NN     50000
#define NE     800000
#define D      128

// Scratch: __device__ globals (no allocations allowed).
__device__ __align__(16) float g_deg[NN];
__device__ __align__(16) float g_h[(size_t)NN * D];   // norm-scaled projected features

static __device__ __forceinline__ int clamp_idx(int v) {
    return v < 0 ? 0 : (v >= NN ? NN - 1 : v);
}

// ---------------------------------------------------------------------------
// Zero scratch + output (d_out is poisoned 0xAA by the harness).
// ---------------------------------------------------------------------------
__global__ void init_kernel(float4* __restrict__ out4) {
    int stride = gridDim.x * blockDim.x;
    int i = blockIdx.x * blockDim.x + threadIdx.x;
    const int total4 = NN * D / 4;
    float4 z = make_float4(0.f, 0.f, 0.f, 0.f);
    for (int t = i; t < total4; t += stride) out4[t] = z;
    for (int t = i; t < NN; t += stride) g_deg[t] = 0.f;
}

// ---------------------------------------------------------------------------
// Degree histogram: deg[r] += 1 for each edge row r.  (indices are int32)
// ---------------------------------------------------------------------------
__global__ void deg_kernel(const int* __restrict__ rows) {
    int e = blockIdx.x * blockDim.x + threadIdx.x;
    if (e < NE) {
        atomicAdd(&g_deg[clamp_idx(rows[e])], 1.0f);
    }
}

// ---------------------------------------------------------------------------
// Register-tiled projection:
//   g_h[base+row][:] = (f[row] @ W) * norm[base+row]
// Block tile: 64 rows x 128 cols. 256 threads, thread tile 8 rows x 4 cols.
// gridDim.y selects type (0 = drug, 1 = disease).
// Dynamic smem: sW[128][128] (64 KB) + sF[64][128] (32 KB) = 96 KB.
// ---------------------------------------------------------------------------
#define BM 64
#define TM 8
#define TN 4
#define PROJ_TB 256

extern __shared__ float s_proj[];

__global__ __launch_bounds__(PROJ_TB, 2)
void proj2_kernel(const float* __restrict__ drug_f, const float* __restrict__ dis_f,
                  const float* __restrict__ drug_w, const float* __restrict__ dis_w) {
    float* sW = s_proj;                 // [128][128]
    float* sF = s_proj + D * D;         // [BM][128]

    const int type = blockIdx.y;
    const float* __restrict__ f = type ? dis_f : drug_f;
    const float* __restrict__ W = type ? dis_w : drug_w;
    const int n_rows   = type ? N_DIS : N_DRUG;
    const int base     = type ? N_DRUG : 0;
    const int row_base = blockIdx.x * BM;

    const int tid = threadIdx.x;
    const int cg  = tid & 31;           // column group: cols cg*4 .. cg*4+3
    const int rg  = tid >> 5;           // row group:    rows rg*8 .. rg*8+7

    // --- Load W tile (full 128x128) ---
    {
        const float4* W4 = (const float4*)W;
        float4* sW4 = (float4*)sW;
        #pragma unroll
        for (int t = 0; t < (D * D / 4) / PROJ_TB; ++t)
            sW4[t * PROJ_TB + tid] = W4[t * PROJ_TB + tid];
    }
    // --- Load f tile (64 rows, row-clamped for the tail block) ---
    {
        float4* sF4 = (float4*)sF;
        #pragma unroll
        for (int t = 0; t < (BM * D / 4) / PROJ_TB; ++t) {
            int idx = t * PROJ_TB + tid;
            int r   = idx >> 5;          // 32 float4 per row
            int k4  = idx & 31;
            int row = row_base + r;
            if (row >= n_rows) row = n_rows - 1;
            sF4[idx] = ((const float4*)f)[(size_t)row * 32 + k4];
        }
    }
    __syncthreads();

    // --- Main loop: 8x4 register tile, 4 k-steps per iteration ---
    float acc[TM][TN];
    #pragma unroll
    for (int i = 0; i < TM; ++i)
        #pragma unroll
        for (int j = 0; j < TN; ++j) acc[i][j] = 0.f;

    const int r0 = rg * TM;
    const int c0 = cg * TN;

    for (int k0 = 0; k0 < D; k0 += 4) {
        float4 a4[TM];
        #pragma unroll
        for (int i = 0; i < TM; ++i)
            a4[i] = *(const float4*)&sF[(r0 + i) * D + k0];   // broadcast across warp
        float4 b4[4];
        #pragma unroll
        for (int kk = 0; kk < 4; ++kk)
            b4[kk] = *(const float4*)&sW[(k0 + kk) * D + c0];
        #pragma unroll
        for (int kk = 0; kk < 4; ++kk) {
            #pragma unroll
            for (int i = 0; i < TM; ++i) {
                float a = (kk == 0) ? a4[i].x : (kk == 1) ? a4[i].y
                        : (kk == 2) ? a4[i].z : a4[i].w;
                acc[i][0] += a * b4[kk].x;
                acc[i][1] += a * b4[kk].y;
                acc[i][2] += a * b4[kk].z;
                acc[i][3] += a * b4[kk].w;
            }
        }
    }

    // --- Scale by norm and store ---
    #pragma unroll
    for (int i = 0; i < TM; ++i) {
        int row = row_base + r0 + i;
        if (row < n_rows) {
            int node = base + row;
            float nrm = rsqrtf(fmaxf(g_deg[node], 1.0f));
            float4 v;
            v.x = acc[i][0] * nrm; v.y = acc[i][1] * nrm;
            v.z = acc[i][2] * nrm; v.w = acc[i][3] * nrm;
            *(float4*)&g_h[(size_t)node * D + c0] = v;
        }
    }
}

// ---------------------------------------------------------------------------
// Scatter: one warp per edge. Gather 128 floats from g_h[col], vector-reduce
// into out[row] with red.global.add.v4.f32 (no return value, L2-resident).
// ---------------------------------------------------------------------------
__global__ __launch_bounds__(256)
void scatter_kernel(const int* __restrict__ rows,
                    const int* __restrict__ cols,
                    float* __restrict__ out) {
    int gw   = (blockIdx.x * blockDim.x + threadIdx.x) >> 5;  // global warp = edge
    int lane = threadIdx.x & 31;
    if (gw >= NE) return;

    int r = clamp_idx(__ldg(&rows[gw]));   // same addr across warp -> broadcast
    int c = clamp_idx(__ldg(&cols[gw]));

    const float4 v = *(const float4*)&g_h[(size_t)c * D + lane * 4];
    float* dst = &out[(size_t)r * D + lane * 4];
    asm volatile("red.global.add.v4.f32 [%0], {%1,%2,%3,%4};"
                 :: "l"(dst), "f"(v.x), "f"(v.y), "f"(v.z), "f"(v.w)
                 : "memory");
}

// ---------------------------------------------------------------------------
// Final symmetric-norm scale: out[i][:] *= norm[i]
// ---------------------------------------------------------------------------
__global__ __launch_bounds__(256)
void scale_kernel(float* __restrict__ out) {
    int idx  = blockIdx.x * blockDim.x + threadIdx.x;  // one per float4
    int row  = idx >> 5;
    int lane = idx & 31;
    if (row >= NN) return;
    float nrm = rsqrtf(fmaxf(g_deg[row], 1.0f));
    float4* p = (float4*)&out[(size_t)row * D + lane * 4];
    float4 v = *p;
    v.x *= nrm; v.y *= nrm; v.z *= nrm; v.w *= nrm;
    *p = v;
}

// ---------------------------------------------------------------------------
// Launch sequence (stream 0, graph-capturable, allocation-free).
// Input order per metadata: drug_f, disease_f, drug_w, disease_w, rows, cols.
// ---------------------------------------------------------------------------
extern "C" void kernel_launch(void* const* d_in, const int* in_sizes, int n_in,
                              void* d_out, int out_size) {
    const float* drug_f = (const float*)d_in[0];
    const float* dis_f  = (const float*)d_in[1];
    const float* drug_w = (const float*)d_in[2];
    const float* dis_w  = (const float*)d_in[3];
    const int*   rows   = (const int*)d_in[4];
    const int*   cols   = (const int*)d_in[5];
    float* out = (float*)d_out;

    // 1) zero deg + output
    init_kernel<<<2048, 256>>>((float4*)out);

    // 2) degree histogram
    deg_kernel<<<(NE + 255) / 256, 256>>>(rows);

    // 3) per-type projection (+ pre-scale by norm), both types in one launch
    const int smem_bytes = (D * D + BM * D) * sizeof(float);   // 96 KB
    (void)cudaFuncSetAttribute(proj2_kernel,
                               cudaFuncAttributeMaxDynamicSharedMemorySize,
                               smem_bytes);
    dim3 pgrid((N_DRUG + BM - 1) / BM, 2);   // N_DRUG == N_DIS rows per type
    proj2_kernel<<<pgrid, PROJ_TB, smem_bytes>>>(drug_f, dis_f, drug_w, dis_w);

    // 4) edge scatter (warp per edge, vector atomics)
    scatter_kernel<<<(NE * 32 + 255) / 256, 256>>>(rows, cols, out);

    // 5) post-scale by norm
    scale_kernel<<<(NN * 32 + 255) / 256, 256>>>(out);
}